// round 5
// baseline (speedup 1.0000x reference)
#include <cuda_runtime.h>

#define N_NODES 100000
#define F0 256
#define F1 128
#define F2 64
#define MAX_E 1600000

// Scratch (allocation-free rule: __device__ globals). 16B-aligned for float4 access.
__device__ int   g_is_i32;
__device__ int   g_deg[N_NODES];
__device__ float g_dinv[N_NODES];
__device__ int   g_row32[MAX_E];
__device__ int   g_col32[MAX_E];
__device__ __align__(16) float g_h1  [N_NODES * F1];  // dinv-scaled hidden layer 1
__device__ __align__(16) float g_acc1[N_NODES * F1];  // layer-1 accumulator / y1 in place
__device__ __align__(16) float g_h2  [N_NODES * F2];  // dinv-scaled hidden layer 2
__device__ __align__(16) float g_acc2[N_NODES * F2];  // layer-2 accumulator (own memory)

// ---------------- init + dtype detection ----------------

__global__ void k_zero_deg() {
    int i = blockIdx.x * blockDim.x + threadIdx.x;
    if (i == 0) g_is_i32 = 0;
    if (i < N_NODES) g_deg[i] = 0;
}

// Interpret the first 256 edge values as int64. If the buffer is really int32,
// each fake int64 packs two node indices (lo + hi*2^32) and is >= 2^32 unless
// hi == 0 (prob 1e-5 per element) -> detection is statistically certain.
__global__ void k_detect(const long long* __restrict__ ei) {
    long long v = ei[threadIdx.x];   // 256 int64 = 2KB; buffer >= 12.8MB either way
    if (v < 0 || v >= N_NODES) g_is_i32 = 1;
}

__global__ void k_prep_edges(const void* __restrict__ eiv, int E) {
    int e = blockIdx.x * blockDim.x + threadIdx.x;
    if (e >= E) return;
    int r, c;
    if (g_is_i32) {
        const int* ei32 = (const int*)eiv;
        r = ei32[e];
        c = ei32[E + e];
    } else {
        const long long* ei64 = (const long long*)eiv;
        r = (int)ei64[e];
        c = (int)ei64[E + e];
    }
    // clamp: any decode bug surfaces as rel_err, never as a fault
    r = min(max(r, 0), N_NODES - 1);
    c = min(max(c, 0), N_NODES - 1);
    g_row32[e] = r;
    g_col32[e] = c;
    atomicAdd(&g_deg[c], 1);
}

__global__ void k_dinv() {
    int i = blockIdx.x * blockDim.x + threadIdx.x;
    if (i < N_NODES) g_dinv[i] = rsqrtf((float)(g_deg[i] + 1));
}

// ---------------- GEMM1: h1s = (x @ W1) * dinv[row]; acc1 = h1s (self-loop init)
// M tile = 64, N = 128 (full), K = 256. 256 threads, each 4x8 outputs.

__global__ void __launch_bounds__(256) k_gemm1(const float* __restrict__ x,
                                               const float* __restrict__ W) {
    __shared__ float As[32][65];   // [k][m], pad -> conflict-free column writes
    __shared__ float Bs[32][128];  // [k][n]
    int tid = threadIdx.x;
    int tx = tid & 15;        // cols tx*8 .. tx*8+7
    int ty = tid >> 4;        // rows ty*4 .. ty*4+3
    int mbase = blockIdx.x * 64;

    float acc[4][8];
#pragma unroll
    for (int i = 0; i < 4; i++)
#pragma unroll
        for (int j = 0; j < 8; j++) acc[i][j] = 0.f;

    for (int kt = 0; kt < F0; kt += 32) {
#pragma unroll
        for (int i = 0; i < 8; i++) {
            int idx = tid + i * 256;
            int k = idx & 31, m = idx >> 5;
            int gm = mbase + m;
            As[k][m] = (gm < N_NODES) ? x[gm * F0 + kt + k] : 0.f;
        }
#pragma unroll
        for (int i = 0; i < 16; i++) {
            int idx = tid + i * 256;
            int n = idx & 127, k = idx >> 7;
            Bs[k][n] = W[(kt + k) * F1 + n];
        }
        __syncthreads();
#pragma unroll
        for (int k = 0; k < 32; k++) {
            float a[4], b[8];
#pragma unroll
            for (int i = 0; i < 4; i++) a[i] = As[k][ty * 4 + i];
#pragma unroll
            for (int j = 0; j < 8; j++) b[j] = Bs[k][tx * 8 + j];
#pragma unroll
            for (int i = 0; i < 4; i++)
#pragma unroll
                for (int j = 0; j < 8; j++) acc[i][j] = fmaf(a[i], b[j], acc[i][j]);
        }
        __syncthreads();
    }

#pragma unroll
    for (int i = 0; i < 4; i++) {
        int gm = mbase + ty * 4 + i;
        if (gm < N_NODES) {
            float s = g_dinv[gm];
#pragma unroll
            for (int j = 0; j < 8; j++) {
                float v = acc[i][j] * s;
                int o = gm * F1 + tx * 8 + j;
                g_h1[o] = v;
                g_acc1[o] = v;   // self-loop term pre-seeded
            }
        }
    }
}

// ---------------- Scatter layer 1: acc1[c] += h1s[r], one warp per edge, float4 per lane

__global__ void __launch_bounds__(256) k_scatter128(int E) {
    int w = (blockIdx.x * blockDim.x + threadIdx.x) >> 5;
    if (w >= E) return;
    int lane = threadIdx.x & 31;
    int r = g_row32[w];
    int c = g_col32[w];
    float4 v = *(const float4*)(g_h1 + r * F1 + lane * 4);
    float* dst = g_acc1 + c * F1 + lane * 4;
    atomicAdd(dst + 0, v.x);
    atomicAdd(dst + 1, v.y);
    atomicAdd(dst + 2, v.z);
    atomicAdd(dst + 3, v.w);
}

// ---------------- y1 = relu(dinv[i]*acc1 + b1)  (in place in g_acc1)

__global__ void k_relu_bias(const float* __restrict__ b1) {
    int idx = blockIdx.x * blockDim.x + threadIdx.x;   // over N*F1/4
    if (idx >= N_NODES * (F1 / 4)) return;
    int i  = idx >> 5;          // node  (F1/4 = 32)
    int j4 = idx & 31;
    float s = g_dinv[i];
    float4 a  = *(float4*)(g_acc1 + i * F1 + j4 * 4);
    float4 bb = *(const float4*)(b1 + j4 * 4);
    a.x = fmaxf(fmaf(s, a.x, bb.x), 0.f);
    a.y = fmaxf(fmaf(s, a.y, bb.y), 0.f);
    a.z = fmaxf(fmaf(s, a.z, bb.z), 0.f);
    a.w = fmaxf(fmaf(s, a.w, bb.w), 0.f);
    *(float4*)(g_acc1 + i * F1 + j4 * 4) = a;
}

// ---------------- GEMM2: h2s = (y1 @ W2) * dinv[row]; acc2 = h2s (self-loop init)
// M tile = 64, N = 64 (full), K = 128. 256 threads, each 4x4 outputs.

__global__ void __launch_bounds__(256) k_gemm2(const float* __restrict__ W) {
    __shared__ float As[32][65];
    __shared__ float Bs[32][64];
    int tid = threadIdx.x;
    int tx = tid & 15;       // cols tx*4 .. tx*4+3
    int ty = tid >> 4;       // rows ty*4 .. ty*4+3
    int mbase = blockIdx.x * 64;

    float acc[4][4];
#pragma unroll
    for (int i = 0; i < 4; i++)
#pragma unroll
        for (int j = 0; j < 4; j++) acc[i][j] = 0.f;

    for (int kt = 0; kt < F1; kt += 32) {
#pragma unroll
        for (int i = 0; i < 8; i++) {
            int idx = tid + i * 256;
            int k = idx & 31, m = idx >> 5;
            int gm = mbase + m;
            As[k][m] = (gm < N_NODES) ? g_acc1[gm * F1 + kt + k] : 0.f;
        }
#pragma unroll
        for (int i = 0; i < 8; i++) {
            int idx = tid + i * 256;
            int n = idx & 63, k = idx >> 6;
            Bs[k][n] = W[(kt + k) * F2 + n];
        }
        __syncthreads();
#pragma unroll
        for (int k = 0; k < 32; k++) {
            float a[4], b[4];
#pragma unroll
            for (int i = 0; i < 4; i++) a[i] = As[k][ty * 4 + i];
#pragma unroll
            for (int j = 0; j < 4; j++) b[j] = Bs[k][tx * 4 + j];
#pragma unroll
            for (int i = 0; i < 4; i++)
#pragma unroll
                for (int j = 0; j < 4; j++) acc[i][j] = fmaf(a[i], b[j], acc[i][j]);
        }
        __syncthreads();
    }

#pragma unroll
    for (int i = 0; i < 4; i++) {
        int gm = mbase + ty * 4 + i;
        if (gm < N_NODES) {
            float s = g_dinv[gm];
#pragma unroll
            for (int j = 0; j < 4; j++) {
                float v = acc[i][j] * s;
                int o = gm * F2 + tx * 4 + j;
                g_h2[o] = v;
                g_acc2[o] = v;   // self-loop init (own memory)
            }
        }
    }
}

// ---------------- Scatter layer 2: acc2[c] += h2s[r], 16 threads per edge

__global__ void __launch_bounds__(256) k_scatter64(int E) {
    int t = blockIdx.x * blockDim.x + threadIdx.x;
    int e = t >> 4;
    if (e >= E) return;
    int sub = t & 15;
    int r = g_row32[e];
    int c = g_col32[e];
    float4 v = *(const float4*)(g_h2 + r * F2 + sub * 4);
    float* dst = g_acc2 + c * F2 + sub * 4;
    atomicAdd(dst + 0, v.x);
    atomicAdd(dst + 1, v.y);
    atomicAdd(dst + 2, v.z);
    atomicAdd(dst + 3, v.w);
}

// ---------------- final: out = dinv[i]*acc2 + b2  (plain stores into d_out only)

__global__ void k_final(float* __restrict__ out, const float* __restrict__ b2) {
    int idx = blockIdx.x * blockDim.x + threadIdx.x;   // over N*F2/4
    if (idx >= N_NODES * (F2 / 4)) return;
    int i  = idx >> 4;          // F2/4 = 16
    int j4 = idx & 15;
    float s = g_dinv[i];
    float4 a  = *(const float4*)(g_acc2 + i * F2 + j4 * 4);
    float4 bb = *(const float4*)(b2 + j4 * 4);
    a.x = fmaf(s, a.x, bb.x);
    a.y = fmaf(s, a.y, bb.y);
    a.z = fmaf(s, a.z, bb.z);
    a.w = fmaf(s, a.w, bb.w);
    out[i * F2 + j4 * 4 + 0] = a.x;
    out[i * F2 + j4 * 4 + 1] = a.y;
    out[i * F2 + j4 * 4 + 2] = a.z;
    out[i * F2 + j4 * 4 + 3] = a.w;
}

extern "C" void kernel_launch(void* const* d_in, const int* in_sizes, int n_in,
                              void* d_out, int out_size) {
    const float* x  = (const float*)d_in[0];
    const void*  ei = d_in[1];
    const float* W1 = (const float*)d_in[2];
    const float* b1 = (const float*)d_in[3];
    const float* W2 = (const float*)d_in[4];
    const float* b2 = (const float*)d_in[5];
    float* out = (float*)d_out;

    int E = in_sizes[1] / 2;
    if (E > MAX_E) E = MAX_E;

    k_zero_deg<<<(N_NODES + 255) / 256, 256>>>();
    k_detect<<<1, 256>>>((const long long*)ei);
    k_prep_edges<<<(E + 255) / 256, 256>>>(ei, E);
    k_dinv<<<(N_NODES + 255) / 256, 256>>>();

    k_gemm1<<<(N_NODES + 63) / 64, 256>>>(x, W1);

    {
        long long threads = (long long)E * 32;
        k_scatter128<<<(unsigned)((threads + 255) / 256), 256>>>(E);
    }

    k_relu_bias<<<(N_NODES * (F1 / 4) + 255) / 256, 256>>>(b1);

    k_gemm2<<<(N_NODES + 63) / 64, 256>>>(W2);

    {
        long long threads = (long long)E * 16;
        k_scatter64<<<(unsigned)((threads + 255) / 256), 256>>>(E);
    }

    k_final<<<(N_NODES * (F2 / 4) + 255) / 256, 256>>>(out, b2);
}

// round 7
// speedup vs baseline: 2.8539x; 2.8539x over previous
#include <cuda_runtime.h>

#define N_NODES 100000
#define F0 256
#define F1 128
#define F2 64
#define MAX_E 1600000
#define NB 391   // ceil(N_NODES/256)

// Scratch (allocation-free rule: __device__ globals). 16B-aligned for float4 access.
__device__ int   g_is_i32;
__device__ int   g_deg[N_NODES];
__device__ float g_dinv[N_NODES];
__device__ int   g_row32[MAX_E];
__device__ int   g_col32[MAX_E];
__device__ int   g_csr[MAX_E];       // source nodes grouped by destination
__device__ int   g_pref[N_NODES];    // scan temp: exclusive prefix within block
__device__ int   g_bsum[NB];
__device__ int   g_boff[NB];
__device__ int   g_rowptr[N_NODES];
__device__ int   g_fill[N_NODES];
__device__ __align__(16) float g_h1[N_NODES * F1];   // dinv-scaled hidden 1
__device__ __align__(16) float g_y1[N_NODES * F1];   // relu output (gemm2 input)
__device__ __align__(16) float g_h2[N_NODES * F2];   // dinv-scaled hidden 2

// ---------------- init + dtype detection + degree ----------------

__global__ void k_zero_deg() {
    int i = blockIdx.x * blockDim.x + threadIdx.x;
    if (i == 0) g_is_i32 = 0;
    if (i < N_NODES) g_deg[i] = 0;
}

// If the buffer is int32, fake-int64 reads pack two indices -> out of range.
__global__ void k_detect(const long long* __restrict__ ei) {
    long long v = ei[threadIdx.x];
    if (v < 0 || v >= N_NODES) g_is_i32 = 1;
}

__global__ void k_prep_edges(const void* __restrict__ eiv, int E) {
    int e = blockIdx.x * blockDim.x + threadIdx.x;
    if (e >= E) return;
    int r, c;
    if (g_is_i32) {
        const int* p = (const int*)eiv;
        r = p[e]; c = p[E + e];
    } else {
        const long long* p = (const long long*)eiv;
        r = (int)p[e]; c = (int)p[E + e];
    }
    r = min(max(r, 0), N_NODES - 1);
    c = min(max(c, 0), N_NODES - 1);
    g_row32[e] = r;
    g_col32[e] = c;
    atomicAdd(&g_deg[c], 1);
}

__global__ void k_dinv() {
    int i = blockIdx.x * blockDim.x + threadIdx.x;
    if (i < N_NODES) g_dinv[i] = rsqrtf((float)(g_deg[i] + 1));
}

// ---------------- CSR build: block scan -> top scan -> add -> fill ----------------

__global__ void k_scan_block() {
    __shared__ int s[256];
    int tid = threadIdx.x;
    int i = blockIdx.x * 256 + tid;
    int v = (i < N_NODES) ? g_deg[i] : 0;
    s[tid] = v;
    __syncthreads();
#pragma unroll
    for (int d = 1; d < 256; d <<= 1) {
        int t = (tid >= d) ? s[tid - d] : 0;
        __syncthreads();
        s[tid] += t;
        __syncthreads();
    }
    if (i < N_NODES) g_pref[i] = s[tid] - v;   // exclusive within block
    if (tid == 255) g_bsum[blockIdx.x] = s[255];
}

__global__ void k_scan_top() {
    __shared__ int s[512];
    int tid = threadIdx.x;
    int v = (tid < NB) ? g_bsum[tid] : 0;
    s[tid] = v;
    __syncthreads();
#pragma unroll
    for (int d = 1; d < 512; d <<= 1) {
        int t = (tid >= d) ? s[tid - d] : 0;
        __syncthreads();
        s[tid] += t;
        __syncthreads();
    }
    if (tid < NB) g_boff[tid] = s[tid] - v;    // exclusive block offsets
}

__global__ void k_scan_add() {
    int i = blockIdx.x * blockDim.x + threadIdx.x;
    if (i < N_NODES) {
        int rp = g_pref[i] + g_boff[i >> 8];
        g_rowptr[i] = rp;
        g_fill[i] = rp;
    }
}

__global__ void k_fill(int E) {
    int e = blockIdx.x * blockDim.x + threadIdx.x;
    if (e >= E) return;
    int c = g_col32[e];
    int pos = atomicAdd(&g_fill[c], 1);
    g_csr[pos] = g_row32[e];
}

// ---------------- GEMM1: g_h1 = (x @ W1) * dinv[row]
// Tile M=128, N=128(full), K step 32. 256 threads, 8x8 outputs each.

__global__ void __launch_bounds__(256) k_gemm1(const float* __restrict__ x,
                                               const float* __restrict__ W) {
    __shared__ float As[32][132];   // [k][m], pad 132 (mult of 4 -> float4-aligned)
    __shared__ float Bs[32][128];   // [k][n]
    int tid = threadIdx.x;
    int tx = tid & 15;        // cols tx*8 .. +7
    int ty = tid >> 4;        // rows ty*8 .. +7
    int mbase = blockIdx.x * 128;

    float acc[8][8];
#pragma unroll
    for (int i = 0; i < 8; i++)
#pragma unroll
        for (int j = 0; j < 8; j++) acc[i][j] = 0.f;

    for (int kt = 0; kt < F0; kt += 32) {
        // A: 128 rows x 32 k = 1024 float4; 4 per thread (float4 along k)
#pragma unroll
        for (int i = 0; i < 4; i++) {
            int idx4 = tid + i * 256;
            int m = idx4 >> 3;             // 8 float4 per row
            int kk = (idx4 & 7) * 4;
            int gm = mbase + m;
            float4 v = make_float4(0.f, 0.f, 0.f, 0.f);
            if (gm < N_NODES) v = *(const float4*)(x + gm * F0 + kt + kk);
            As[kk + 0][m] = v.x;
            As[kk + 1][m] = v.y;
            As[kk + 2][m] = v.z;
            As[kk + 3][m] = v.w;
        }
        // B: 32 k x 128 n = 1024 float4; 4 per thread (float4 along n)
#pragma unroll
        for (int i = 0; i < 4; i++) {
            int idx4 = tid + i * 256;
            int k = idx4 >> 5;             // 32 float4 per row
            int nn = (idx4 & 31) * 4;
            *(float4*)(&Bs[k][nn]) = *(const float4*)(W + (kt + k) * F1 + nn);
        }
        __syncthreads();
#pragma unroll
        for (int k = 0; k < 32; k++) {
            float a[8], b[8];
            *(float4*)(a)     = *(const float4*)(&As[k][ty * 8]);
            *(float4*)(a + 4) = *(const float4*)(&As[k][ty * 8 + 4]);
            *(float4*)(b)     = *(const float4*)(&Bs[k][tx * 8]);
            *(float4*)(b + 4) = *(const float4*)(&Bs[k][tx * 8 + 4]);
#pragma unroll
            for (int i = 0; i < 8; i++)
#pragma unroll
                for (int j = 0; j < 8; j++) acc[i][j] = fmaf(a[i], b[j], acc[i][j]);
        }
        __syncthreads();
    }

#pragma unroll
    for (int i = 0; i < 8; i++) {
        int gm = mbase + ty * 8 + i;
        if (gm < N_NODES) {
            float s = g_dinv[gm];
#pragma unroll
            for (int j = 0; j < 8; j += 4) {
                float4 v;
                v.x = acc[i][j + 0] * s;
                v.y = acc[i][j + 1] * s;
                v.z = acc[i][j + 2] * s;
                v.w = acc[i][j + 3] * s;
                *(float4*)(g_h1 + gm * F1 + tx * 8 + j) = v;
            }
        }
    }
}

// ---------------- Gather layer 1 (fused agg + relu + bias): warp per node
// y1[c] = relu(dinv[c] * (g_h1[c] + sum_{r->c} g_h1[r]) + b1)

__global__ void __launch_bounds__(256) k_gather1(const float* __restrict__ b1) {
    int w = (blockIdx.x * blockDim.x + threadIdx.x) >> 5;
    if (w >= N_NODES) return;
    int lane = threadIdx.x & 31;
    int c = w;

    float4 acc = *(const float4*)(g_h1 + c * F1 + lane * 4);  // self-loop term
    int start = g_rowptr[c];
    int end = start + g_deg[c];

    int j = start;
    for (; j + 1 < end; j += 2) {   // 2-way unroll for MLP
        int s0 = g_csr[j];
        int s1 = g_csr[j + 1];
        float4 v0 = *(const float4*)(g_h1 + s0 * F1 + lane * 4);
        float4 v1 = *(const float4*)(g_h1 + s1 * F1 + lane * 4);
        acc.x += v0.x + v1.x;
        acc.y += v0.y + v1.y;
        acc.z += v0.z + v1.z;
        acc.w += v0.w + v1.w;
    }
    if (j < end) {
        int s0 = g_csr[j];
        float4 v0 = *(const float4*)(g_h1 + s0 * F1 + lane * 4);
        acc.x += v0.x; acc.y += v0.y; acc.z += v0.z; acc.w += v0.w;
    }

    float s = g_dinv[c];
    float4 bb = *(const float4*)(b1 + lane * 4);
    acc.x = fmaxf(fmaf(s, acc.x, bb.x), 0.f);
    acc.y = fmaxf(fmaf(s, acc.y, bb.y), 0.f);
    acc.z = fmaxf(fmaf(s, acc.z, bb.z), 0.f);
    acc.w = fmaxf(fmaf(s, acc.w, bb.w), 0.f);
    *(float4*)(g_y1 + c * F1 + lane * 4) = acc;
}

// ---------------- GEMM2: g_h2 = (y1 @ W2) * dinv[row]
// Tile M=128, N=64(full), K step 32. 256 threads, 8x4 outputs each.

__global__ void __launch_bounds__(256) k_gemm2(const float* __restrict__ W) {
    __shared__ float As[32][132];
    __shared__ float Bs[32][64];
    int tid = threadIdx.x;
    int tx = tid & 15;       // cols tx*4 .. +3
    int ty = tid >> 4;       // rows ty*8 .. +7
    int mbase = blockIdx.x * 128;

    float acc[8][4];
#pragma unroll
    for (int i = 0; i < 8; i++)
#pragma unroll
        for (int j = 0; j < 4; j++) acc[i][j] = 0.f;

    for (int kt = 0; kt < F1; kt += 32) {
#pragma unroll
        for (int i = 0; i < 4; i++) {
            int idx4 = tid + i * 256;
            int m = idx4 >> 3;
            int kk = (idx4 & 7) * 4;
            int gm = mbase + m;
            float4 v = make_float4(0.f, 0.f, 0.f, 0.f);
            if (gm < N_NODES) v = *(const float4*)(g_y1 + gm * F1 + kt + kk);
            As[kk + 0][m] = v.x;
            As[kk + 1][m] = v.y;
            As[kk + 2][m] = v.z;
            As[kk + 3][m] = v.w;
        }
        // B: 32 k x 64 n = 512 float4; 2 per thread (FIXED: cover idx4 0..511)
#pragma unroll
        for (int i = 0; i < 2; i++) {
            int idx4 = tid + i * 256;
            int k = idx4 >> 4;             // 16 float4 per row -> k in 0..31
            int nn = (idx4 & 15) * 4;
            *(float4*)(&Bs[k][nn]) = *(const float4*)(W + (kt + k) * F2 + nn);
        }
        __syncthreads();
#pragma unroll
        for (int k = 0; k < 32; k++) {
            float a[8], b[4];
            *(float4*)(a)     = *(const float4*)(&As[k][ty * 8]);
            *(float4*)(a + 4) = *(const float4*)(&As[k][ty * 8 + 4]);
            *(float4*)(b)     = *(const float4*)(&Bs[k][tx * 4]);
#pragma unroll
            for (int i = 0; i < 8; i++)
#pragma unroll
                for (int j = 0; j < 4; j++) acc[i][j] = fmaf(a[i], b[j], acc[i][j]);
        }
        __syncthreads();
    }

#pragma unroll
    for (int i = 0; i < 8; i++) {
        int gm = mbase + ty * 8 + i;
        if (gm < N_NODES) {
            float s = g_dinv[gm];
            float4 v;
            v.x = acc[i][0] * s;
            v.y = acc[i][1] * s;
            v.z = acc[i][2] * s;
            v.w = acc[i][3] * s;
            *(float4*)(g_h2 + gm * F2 + tx * 4) = v;
        }
    }
}

// ---------------- Gather layer 2 (fused agg + bias): warp per node, float2 per lane
// out[c] = dinv[c] * (g_h2[c] + sum_{r->c} g_h2[r]) + b2

__global__ void __launch_bounds__(256) k_gather2(float* __restrict__ out,
                                                 const float* __restrict__ b2) {
    int w = (blockIdx.x * blockDim.x + threadIdx.x) >> 5;
    if (w >= N_NODES) return;
    int lane = threadIdx.x & 31;
    int c = w;

    float2 acc = *(const float2*)(g_h2 + c * F2 + lane * 2);
    int start = g_rowptr[c];
    int end = start + g_deg[c];

    int j = start;
    for (; j + 1 < end; j += 2) {
        int s0 = g_csr[j];
        int s1 = g_csr[j + 1];
        float2 v0 = *(const float2*)(g_h2 + s0 * F2 + lane * 2);
        float2 v1 = *(const float2*)(g_h2 + s1 * F2 + lane * 2);
        acc.x += v0.x + v1.x;
        acc.y += v0.y + v1.y;
    }
    if (j < end) {
        int s0 = g_csr[j];
        float2 v0 = *(const float2*)(g_h2 + s0 * F2 + lane * 2);
        acc.x += v0.x; acc.y += v0.y;
    }

    float s = g_dinv[c];
    float2 bb = *(const float2*)(b2 + lane * 2);
    out[c * F2 + lane * 2 + 0] = fmaf(s, acc.x, bb.x);
    out[c * F2 + lane * 2 + 1] = fmaf(s, acc.y, bb.y);
}

extern "C" void kernel_launch(void* const* d_in, const int* in_sizes, int n_in,
                              void* d_out, int out_size) {
    const float* x  = (const float*)d_in[0];
    const void*  ei = d_in[1];
    const float* W1 = (const float*)d_in[2];
    const float* b1 = (const float*)d_in[3];
    const float* W2 = (const float*)d_in[4];
    const float* b2 = (const float*)d_in[5];
    float* out = (float*)d_out;

    int E = in_sizes[1] / 2;
    if (E > MAX_E) E = MAX_E;

    k_zero_deg<<<(N_NODES + 255) / 256, 256>>>();
    k_detect<<<1, 256>>>((const long long*)ei);
    k_prep_edges<<<(E + 255) / 256, 256>>>(ei, E);
    k_dinv<<<(N_NODES + 255) / 256, 256>>>();

    k_scan_block<<<NB, 256>>>();
    k_scan_top<<<1, 512>>>();
    k_scan_add<<<(N_NODES + 255) / 256, 256>>>();
    k_fill<<<(E + 255) / 256, 256>>>(E);

    k_gemm1<<<(N_NODES + 127) / 128, 256>>>(x, W1);
    k_gather1<<<(N_NODES * 32 + 255) / 256, 256>>>(b1);
    k_gemm2<<<(N_NODES + 127) / 128, 256>>>(W2);
    k_gather2<<<(N_NODES * 32 + 255) / 256, 256>>>(out, b2);
}

// round 8
// speedup vs baseline: 4.2940x; 1.5046x over previous
#include <cuda_runtime.h>

#define N_NODES 100000
#define F0 256
#define F1 128
#define F2 64
#define MAX_E 1600000
#define NB 391   // ceil(N_NODES/256)

// Scratch (allocation-free rule: __device__ globals). 16B-aligned for float4 access.
__device__ int   g_is_i32;
__device__ int   g_deg[N_NODES];
__device__ float g_dinv[N_NODES];
__device__ int   g_row32[MAX_E];
__device__ int   g_col32[MAX_E];
__device__ int   g_csr[MAX_E];       // source nodes grouped by destination
__device__ int   g_pref[N_NODES];
__device__ int   g_bsum[NB];
__device__ int   g_boff[NB];
__device__ int   g_rowptr[N_NODES];
__device__ int   g_fill[N_NODES];
__device__ __align__(16) float g_h1[N_NODES * F1];   // dinv-scaled hidden 1
__device__ __align__(16) float g_y1[N_NODES * F1];   // relu output (gemm2 input)
__device__ __align__(16) float g_h2[N_NODES * F2];   // dinv-scaled hidden 2

// ---------------- tf32 helpers ----------------

__device__ __forceinline__ unsigned f2tf32(float f) {
    unsigned u;
    asm("cvt.rna.tf32.f32 %0, %1;" : "=r"(u) : "f"(f));
    return u;
}

__device__ __forceinline__ void mma_tf32(float* c, const unsigned* a, const unsigned* b) {
    asm volatile(
        "mma.sync.aligned.m16n8k8.row.col.f32.tf32.tf32.f32 "
        "{%0,%1,%2,%3}, {%4,%5,%6,%7}, {%8,%9}, {%0,%1,%2,%3};\n"
        : "+f"(c[0]), "+f"(c[1]), "+f"(c[2]), "+f"(c[3])
        : "r"(a[0]), "r"(a[1]), "r"(a[2]), "r"(a[3]), "r"(b[0]), "r"(b[1]));
}

// ---------------- init + dtype detection + degree ----------------

__global__ void k_zero_deg() {
    int i = blockIdx.x * blockDim.x + threadIdx.x;
    if (i == 0) g_is_i32 = 0;
    if (i < N_NODES) g_deg[i] = 0;
}

__global__ void k_detect(const long long* __restrict__ ei) {
    long long v = ei[threadIdx.x];
    if (v < 0 || v >= N_NODES) g_is_i32 = 1;
}

__global__ void k_prep_edges(const void* __restrict__ eiv, int E) {
    int e = blockIdx.x * blockDim.x + threadIdx.x;
    if (e >= E) return;
    int r, c;
    if (g_is_i32) {
        const int* p = (const int*)eiv;
        r = p[e]; c = p[E + e];
    } else {
        const long long* p = (const long long*)eiv;
        r = (int)p[e]; c = (int)p[E + e];
    }
    r = min(max(r, 0), N_NODES - 1);
    c = min(max(c, 0), N_NODES - 1);
    g_row32[e] = r;
    g_col32[e] = c;
    atomicAdd(&g_deg[c], 1);
}

__global__ void k_dinv() {
    int i = blockIdx.x * blockDim.x + threadIdx.x;
    if (i < N_NODES) g_dinv[i] = rsqrtf((float)(g_deg[i] + 1));
}

// ---------------- CSR build: block scan -> top scan -> add -> fill ----------------

__global__ void k_scan_block() {
    __shared__ int s[256];
    int tid = threadIdx.x;
    int i = blockIdx.x * 256 + tid;
    int v = (i < N_NODES) ? g_deg[i] : 0;
    s[tid] = v;
    __syncthreads();
#pragma unroll
    for (int d = 1; d < 256; d <<= 1) {
        int t = (tid >= d) ? s[tid - d] : 0;
        __syncthreads();
        s[tid] += t;
        __syncthreads();
    }
    if (i < N_NODES) g_pref[i] = s[tid] - v;
    if (tid == 255) g_bsum[blockIdx.x] = s[255];
}

__global__ void k_scan_top() {
    __shared__ int s[512];
    int tid = threadIdx.x;
    int v = (tid < NB) ? g_bsum[tid] : 0;
    s[tid] = v;
    __syncthreads();
#pragma unroll
    for (int d = 1; d < 512; d <<= 1) {
        int t = (tid >= d) ? s[tid - d] : 0;
        __syncthreads();
        s[tid] += t;
        __syncthreads();
    }
    if (tid < NB) g_boff[tid] = s[tid] - v;
}

__global__ void k_scan_add() {
    int i = blockIdx.x * blockDim.x + threadIdx.x;
    if (i < N_NODES) {
        int rp = g_pref[i] + g_boff[i >> 8];
        g_rowptr[i] = rp;
        g_fill[i] = rp;
    }
}

__global__ void k_fill(int E) {
    int e = blockIdx.x * blockDim.x + threadIdx.x;
    if (e >= E) return;
    int c = g_col32[e];
    int pos = atomicAdd(&g_fill[c], 1);
    g_csr[pos] = g_row32[e];
}

// ---------------- GEMM1 (tf32 mma): g_h1 = (x @ W1) * dinv[row]
// Block tile 128x128, 8 warps in 4(m) x 2(n), warp tile 32x64.

__global__ void __launch_bounds__(256) k_gemm1(const float* __restrict__ x,
                                               const float* __restrict__ W) {
    __shared__ unsigned As[128][36];   // [m][k], tf32 bits; banks (4m+k)%32 distinct
    __shared__ unsigned Bs[32][132];   // [k][n], tf32 bits
    int tid = threadIdx.x;
    int lane = tid & 31;
    int wid = tid >> 5;
    int warp_m = wid & 3;    // 0..3 -> rows warp_m*32
    int warp_n = wid >> 2;   // 0..1 -> cols warp_n*64
    int grp = lane >> 2;     // 0..7
    int thr = lane & 3;      // 0..3
    int mbase = blockIdx.x * 128;

    float acc[2][8][4];
#pragma unroll
    for (int mf = 0; mf < 2; mf++)
#pragma unroll
        for (int nf = 0; nf < 8; nf++)
#pragma unroll
            for (int q = 0; q < 4; q++) acc[mf][nf][q] = 0.f;

    for (int kt = 0; kt < F0; kt += 32) {
        // A: 128 rows x 32 k = 1024 float4; 4 per thread; store [m][k]
#pragma unroll
        for (int i = 0; i < 4; i++) {
            int idx4 = tid + i * 256;
            int m = idx4 >> 3;
            int kk = (idx4 & 7) * 4;
            int gm = mbase + m;
            float4 v = make_float4(0.f, 0.f, 0.f, 0.f);
            if (gm < N_NODES) v = *(const float4*)(x + gm * F0 + kt + kk);
            uint4 u;
            u.x = f2tf32(v.x); u.y = f2tf32(v.y); u.z = f2tf32(v.z); u.w = f2tf32(v.w);
            *(uint4*)(&As[m][kk]) = u;
        }
        // B: 32 k x 128 n = 1024 float4; 4 per thread; store [k][n]
#pragma unroll
        for (int i = 0; i < 4; i++) {
            int idx4 = tid + i * 256;
            int k = idx4 >> 5;
            int nn = (idx4 & 31) * 4;
            float4 v = *(const float4*)(W + (kt + k) * F1 + nn);
            uint4 u;
            u.x = f2tf32(v.x); u.y = f2tf32(v.y); u.z = f2tf32(v.z); u.w = f2tf32(v.w);
            *(uint4*)(&Bs[k][nn]) = u;
        }
        __syncthreads();

#pragma unroll
        for (int k0 = 0; k0 < 32; k0 += 8) {
            unsigned a[2][4];
#pragma unroll
            for (int mf = 0; mf < 2; mf++) {
                int r = warp_m * 32 + mf * 16 + grp;
                a[mf][0] = As[r][k0 + thr];
                a[mf][1] = As[r + 8][k0 + thr];
                a[mf][2] = As[r][k0 + 4 + thr];
                a[mf][3] = As[r + 8][k0 + 4 + thr];
            }
            unsigned b[8][2];
#pragma unroll
            for (int nf = 0; nf < 8; nf++) {
                int cNo = warp_n * 64 + nf * 8 + grp;
                b[nf][0] = Bs[k0 + thr][cNo];
                b[nf][1] = Bs[k0 + 4 + thr][cNo];
            }
#pragma unroll
            for (int mf = 0; mf < 2; mf++)
#pragma unroll
                for (int nf = 0; nf < 8; nf++)
                    mma_tf32(acc[mf][nf], a[mf], b[nf]);
        }
        __syncthreads();
    }

    // Epilogue: scale rows by dinv, store float2 per fragment half
#pragma unroll
    for (int mf = 0; mf < 2; mf++) {
        int r0 = mbase + warp_m * 32 + mf * 16 + grp;
        int r1 = r0 + 8;
        float s0 = (r0 < N_NODES) ? g_dinv[r0] : 0.f;
        float s1 = (r1 < N_NODES) ? g_dinv[r1] : 0.f;
#pragma unroll
        for (int nf = 0; nf < 8; nf++) {
            int cNo = warp_n * 64 + nf * 8 + thr * 2;
            if (r0 < N_NODES) {
                float2 v = make_float2(acc[mf][nf][0] * s0, acc[mf][nf][1] * s0);
                *(float2*)(g_h1 + r0 * F1 + cNo) = v;
            }
            if (r1 < N_NODES) {
                float2 v = make_float2(acc[mf][nf][2] * s1, acc[mf][nf][3] * s1);
                *(float2*)(g_h1 + r1 * F1 + cNo) = v;
            }
        }
    }
}

// ---------------- Gather layer 1 (fused agg + relu + bias): warp per node

__global__ void __launch_bounds__(256) k_gather1(const float* __restrict__ b1) {
    int w = (blockIdx.x * blockDim.x + threadIdx.x) >> 5;
    if (w >= N_NODES) return;
    int lane = threadIdx.x & 31;
    int c = w;

    float4 acc = *(const float4*)(g_h1 + c * F1 + lane * 4);  // self-loop term
    int start = g_rowptr[c];
    int end = start + g_deg[c];

    int j = start;
    for (; j + 1 < end; j += 2) {
        int s0 = g_csr[j];
        int s1 = g_csr[j + 1];
        float4 v0 = *(const float4*)(g_h1 + s0 * F1 + lane * 4);
        float4 v1 = *(const float4*)(g_h1 + s1 * F1 + lane * 4);
        acc.x += v0.x + v1.x;
        acc.y += v0.y + v1.y;
        acc.z += v0.z + v1.z;
        acc.w += v0.w + v1.w;
    }
    if (j < end) {
        int s0 = g_csr[j];
        float4 v0 = *(const float4*)(g_h1 + s0 * F1 + lane * 4);
        acc.x += v0.x; acc.y += v0.y; acc.z += v0.z; acc.w += v0.w;
    }

    float s = g_dinv[c];
    float4 bb = *(const float4*)(b1 + lane * 4);
    acc.x = fmaxf(fmaf(s, acc.x, bb.x), 0.f);
    acc.y = fmaxf(fmaf(s, acc.y, bb.y), 0.f);
    acc.z = fmaxf(fmaf(s, acc.z, bb.z), 0.f);
    acc.w = fmaxf(fmaf(s, acc.w, bb.w), 0.f);
    *(float4*)(g_y1 + c * F1 + lane * 4) = acc;
}

// ---------------- GEMM2 (tf32 mma): g_h2 = (y1 @ W2) * dinv[row]
// Block tile 128x64, 8 warps in 8(m) x 1(n), warp tile 16x64.

__global__ void __launch_bounds__(256) k_gemm2(const float* __restrict__ W) {
    __shared__ unsigned As[128][36];   // [m][k]
    __shared__ unsigned Bs[32][68];    // [k][n]
    int tid = threadIdx.x;
    int lane = tid & 31;
    int wid = tid >> 5;      // warp_m = wid, rows wid*16
    int grp = lane >> 2;
    int thr = lane & 3;
    int mbase = blockIdx.x * 128;

    float acc[8][4];
#pragma unroll
    for (int nf = 0; nf < 8; nf++)
#pragma unroll
        for (int q = 0; q < 4; q++) acc[nf][q] = 0.f;

    for (int kt = 0; kt < F1; kt += 32) {
        // A: 128 x 32 = 1024 float4; 4 per thread
#pragma unroll
        for (int i = 0; i < 4; i++) {
            int idx4 = tid + i * 256;
            int m = idx4 >> 3;
            int kk = (idx4 & 7) * 4;
            int gm = mbase + m;
            float4 v = make_float4(0.f, 0.f, 0.f, 0.f);
            if (gm < N_NODES) v = *(const float4*)(g_y1 + gm * F1 + kt + kk);
            uint4 u;
            u.x = f2tf32(v.x); u.y = f2tf32(v.y); u.z = f2tf32(v.z); u.w = f2tf32(v.w);
            *(uint4*)(&As[m][kk]) = u;
        }
        // B: 32 x 64 = 512 float4; 2 per thread (k = idx4>>4 covers 0..31)
#pragma unroll
        for (int i = 0; i < 2; i++) {
            int idx4 = tid + i * 256;
            int k = idx4 >> 4;
            int nn = (idx4 & 15) * 4;
            float4 v = *(const float4*)(W + (kt + k) * F2 + nn);
            uint4 u;
            u.x = f2tf32(v.x); u.y = f2tf32(v.y); u.z = f2tf32(v.z); u.w = f2tf32(v.w);
            *(uint4*)(&Bs[k][nn]) = u;
        }
        __syncthreads();

#pragma unroll
        for (int k0 = 0; k0 < 32; k0 += 8) {
            unsigned a[4];
            int r = wid * 16 + grp;
            a[0] = As[r][k0 + thr];
            a[1] = As[r + 8][k0 + thr];
            a[2] = As[r][k0 + 4 + thr];
            a[3] = As[r + 8][k0 + 4 + thr];
            unsigned b[8][2];
#pragma unroll
            for (int nf = 0; nf < 8; nf++) {
                int cNo = nf * 8 + grp;
                b[nf][0] = Bs[k0 + thr][cNo];
                b[nf][1] = Bs[k0 + 4 + thr][cNo];
            }
#pragma unroll
            for (int nf = 0; nf < 8; nf++)
                mma_tf32(acc[nf], a, b[nf]);
        }
        __syncthreads();
    }

    int r0 = mbase + wid * 16 + grp;
    int r1 = r0 + 8;
    float s0 = (r0 < N_NODES) ? g_dinv[r0] : 0.f;
    float s1 = (r1 < N_NODES) ? g_dinv[r1] : 0.f;
#pragma unroll
    for (int nf = 0; nf < 8; nf++) {
        int cNo = nf * 8 + thr * 2;
        if (r0 < N_NODES) {
            float2 v = make_float2(acc[nf][0] * s0, acc[nf][1] * s0);
            *(float2*)(g_h2 + r0 * F2 + cNo) = v;
        }
        if (r1 < N_NODES) {
            float2 v = make_float2(acc[nf][2] * s1, acc[nf][3] * s1);
            *(float2*)(g_h2 + r1 * F2 + cNo) = v;
        }
    }
}

// ---------------- Gather layer 2 (fused agg + bias): warp per node

__global__ void __launch_bounds__(256) k_gather2(float* __restrict__ out,
                                                 const float* __restrict__ b2) {
    int w = (blockIdx.x * blockDim.x + threadIdx.x) >> 5;
    if (w >= N_NODES) return;
    int lane = threadIdx.x & 31;
    int c = w;

    float2 acc = *(const float2*)(g_h2 + c * F2 + lane * 2);
    int start = g_rowptr[c];
    int end = start + g_deg[c];

    int j = start;
    for (; j + 1 < end; j += 2) {
        int s0 = g_csr[j];
        int s1 = g_csr[j + 1];
        float2 v0 = *(const float2*)(g_h2 + s0 * F2 + lane * 2);
        float2 v1 = *(const float2*)(g_h2 + s1 * F2 + lane * 2);
        acc.x += v0.x + v1.x;
        acc.y += v0.y + v1.y;
    }
    if (j < end) {
        int s0 = g_csr[j];
        float2 v0 = *(const float2*)(g_h2 + s0 * F2 + lane * 2);
        acc.x += v0.x; acc.y += v0.y;
    }

    float s = g_dinv[c];
    float2 bb = *(const float2*)(b2 + lane * 2);
    out[c * F2 + lane * 2 + 0] = fmaf(s, acc.x, bb.x);
    out[c * F2 + lane * 2 + 1] = fmaf(s, acc.y, bb.y);
}

extern "C" void kernel_launch(void* const* d_in, const int* in_sizes, int n_in,
                              void* d_out, int out_size) {
    const float* x  = (const float*)d_in[0];
    const void*  ei = d_in[1];
    const float* W1 = (const float*)d_in[2];
    const float* b1 = (const float*)d_in[3];
    const float* W2 = (const float*)d_in[4];
    const float* b2 = (const float*)d_in[5];
    float* out = (float*)d_out;

    int E = in_sizes[1] / 2;
    if (E > MAX_E) E = MAX_E;

    k_zero_deg<<<(N_NODES + 255) / 256, 256>>>();
    k_detect<<<1, 256>>>((const long long*)ei);
    k_prep_edges<<<(E + 255) / 256, 256>>>(ei, E);
    k_dinv<<<(N_NODES + 255) / 256, 256>>>();

    k_scan_block<<<NB, 256>>>();
    k_scan_top<<<1, 512>>>();
    k_scan_add<<<(N_NODES + 255) / 256, 256>>>();
    k_fill<<<(E + 255) / 256, 256>>>(E);

    k_gemm1<<<(N_NODES + 127) / 128, 256>>>(x, W1);
    k_gather1<<<(N_NODES * 32 + 255) / 256, 256>>>(b1);
    k_gemm2<<<(N_NODES + 127) / 128, 256>>>(W2);
    k_gather2<<<(N_NODES * 32 + 255) / 256, 256>>>(out, b2);
}

// round 10
// speedup vs baseline: 4.3949x; 1.0235x over previous
#include <cuda_runtime.h>
#include <cuda_fp16.h>

#define N_NODES 100000
#define F0 256
#define F1 128
#define F2 64
#define MAX_E 1600000
#define NB 391   // ceil(N_NODES/256)

// Scratch (allocation-free rule: __device__ globals). 16B-aligned for vector access.
__device__ int   g_is_i32;
__device__ int   g_deg[N_NODES];
__device__ float g_dinv[N_NODES];
__device__ int   g_row32[MAX_E];
__device__ int   g_col32[MAX_E];
__device__ int   g_csr[MAX_E];       // source nodes grouped by destination
__device__ int   g_pref[N_NODES];
__device__ int   g_bsum[NB];
__device__ int   g_boff[NB];
__device__ int   g_rowptr[N_NODES];
__device__ int   g_fill[N_NODES];
__device__ __align__(16) __half g_h1[N_NODES * F1];  // dinv-scaled hidden 1 (fp16)
__device__ __align__(16) __half g_y1[N_NODES * F1];  // relu output (fp16, gemm2 input)
__device__ __align__(16) __half g_h2[N_NODES * F2];  // dinv-scaled hidden 2 (fp16)

// ---------------- tf32 helpers ----------------

__device__ __forceinline__ unsigned f2tf32(float f) {
    unsigned u;
    asm("cvt.rna.tf32.f32 %0, %1;" : "=r"(u) : "f"(f));
    return u;
}

__device__ __forceinline__ void mma_tf32(float* c, const unsigned* a, const unsigned* b) {
    asm volatile(
        "mma.sync.aligned.m16n8k8.row.col.f32.tf32.tf32.f32 "
        "{%0,%1,%2,%3}, {%4,%5,%6,%7}, {%8,%9}, {%0,%1,%2,%3};\n"
        : "+f"(c[0]), "+f"(c[1]), "+f"(c[2]), "+f"(c[3])
        : "r"(a[0]), "r"(a[1]), "r"(a[2]), "r"(a[3]), "r"(b[0]), "r"(b[1]));
}

// ---------------- init + dtype detection + degree ----------------

__global__ void k_zero_deg() {
    int i = blockIdx.x * blockDim.x + threadIdx.x;
    if (i == 0) g_is_i32 = 0;
    if (i < N_NODES) g_deg[i] = 0;
}

__global__ void k_detect(const long long* __restrict__ ei) {
    long long v = ei[threadIdx.x];
    if (v < 0 || v >= N_NODES) g_is_i32 = 1;
}

__global__ void k_prep_edges(const void* __restrict__ eiv, int E) {
    int e = blockIdx.x * blockDim.x + threadIdx.x;
    if (e >= E) return;
    int r, c;
    if (g_is_i32) {
        const int* p = (const int*)eiv;
        r = p[e]; c = p[E + e];
    } else {
        const long long* p = (const long long*)eiv;
        r = (int)p[e]; c = (int)p[E + e];
    }
    r = min(max(r, 0), N_NODES - 1);
    c = min(max(c, 0), N_NODES - 1);
    g_row32[e] = r;
    g_col32[e] = c;
    atomicAdd(&g_deg[c], 1);
}

__global__ void k_dinv() {
    int i = blockIdx.x * blockDim.x + threadIdx.x;
    if (i < N_NODES) g_dinv[i] = rsqrtf((float)(g_deg[i] + 1));
}

// ---------------- CSR build: block scan -> top scan -> add -> fill ----------------

__global__ void k_scan_block() {
    __shared__ int s[256];
    int tid = threadIdx.x;
    int i = blockIdx.x * 256 + tid;
    int v = (i < N_NODES) ? g_deg[i] : 0;
    s[tid] = v;
    __syncthreads();
#pragma unroll
    for (int d = 1; d < 256; d <<= 1) {
        int t = (tid >= d) ? s[tid - d] : 0;
        __syncthreads();
        s[tid] += t;
        __syncthreads();
    }
    if (i < N_NODES) g_pref[i] = s[tid] - v;
    if (tid == 255) g_bsum[blockIdx.x] = s[255];
}

__global__ void k_scan_top() {
    __shared__ int s[512];
    int tid = threadIdx.x;
    int v = (tid < NB) ? g_bsum[tid] : 0;
    s[tid] = v;
    __syncthreads();
#pragma unroll
    for (int d = 1; d < 512; d <<= 1) {
        int t = (tid >= d) ? s[tid - d] : 0;
        __syncthreads();
        s[tid] += t;
        __syncthreads();
    }
    if (tid < NB) g_boff[tid] = s[tid] - v;
}

__global__ void k_scan_add() {
    int i = blockIdx.x * blockDim.x + threadIdx.x;
    if (i < N_NODES) {
        int rp = g_pref[i] + g_boff[i >> 8];
        g_rowptr[i] = rp;
        g_fill[i] = rp;
    }
}

__global__ void k_fill(int E) {
    int e = blockIdx.x * blockDim.x + threadIdx.x;
    if (e >= E) return;
    int c = g_col32[e];
    int pos = atomicAdd(&g_fill[c], 1);
    g_csr[pos] = g_row32[e];
}

// ---------------- GEMM1 (tf32 mma): g_h1 = fp16( (x @ W1) * dinv[row] )
// Block tile 128x128, 8 warps in 4(m) x 2(n), warp tile 32x64.

__global__ void __launch_bounds__(256) k_gemm1(const float* __restrict__ x,
                                               const float* __restrict__ W) {
    __shared__ unsigned As[128][36];   // [m][k], tf32 bits
    __shared__ unsigned Bs[32][132];   // [k][n], tf32 bits
    int tid = threadIdx.x;
    int lane = tid & 31;
    int wid = tid >> 5;
    int warp_m = wid & 3;
    int warp_n = wid >> 2;
    int grp = lane >> 2;
    int thr = lane & 3;
    int mbase = blockIdx.x * 128;

    float acc[2][8][4];
#pragma unroll
    for (int mf = 0; mf < 2; mf++)
#pragma unroll
        for (int nf = 0; nf < 8; nf++)
#pragma unroll
            for (int q = 0; q < 4; q++) acc[mf][nf][q] = 0.f;

    for (int kt = 0; kt < F0; kt += 32) {
#pragma unroll
        for (int i = 0; i < 4; i++) {
            int idx4 = tid + i * 256;
            int m = idx4 >> 3;
            int kk = (idx4 & 7) * 4;
            int gm = mbase + m;
            float4 v = make_float4(0.f, 0.f, 0.f, 0.f);
            if (gm < N_NODES) v = *(const float4*)(x + gm * F0 + kt + kk);
            uint4 u;
            u.x = f2tf32(v.x); u.y = f2tf32(v.y); u.z = f2tf32(v.z); u.w = f2tf32(v.w);
            *(uint4*)(&As[m][kk]) = u;
        }
#pragma unroll
        for (int i = 0; i < 4; i++) {
            int idx4 = tid + i * 256;
            int k = idx4 >> 5;
            int nn = (idx4 & 31) * 4;
            float4 v = *(const float4*)(W + (kt + k) * F1 + nn);
            uint4 u;
            u.x = f2tf32(v.x); u.y = f2tf32(v.y); u.z = f2tf32(v.z); u.w = f2tf32(v.w);
            *(uint4*)(&Bs[k][nn]) = u;
        }
        __syncthreads();

#pragma unroll
        for (int k0 = 0; k0 < 32; k0 += 8) {
            unsigned a[2][4];
#pragma unroll
            for (int mf = 0; mf < 2; mf++) {
                int r = warp_m * 32 + mf * 16 + grp;
                a[mf][0] = As[r][k0 + thr];
                a[mf][1] = As[r + 8][k0 + thr];
                a[mf][2] = As[r][k0 + 4 + thr];
                a[mf][3] = As[r + 8][k0 + 4 + thr];
            }
            unsigned b[8][2];
#pragma unroll
            for (int nf = 0; nf < 8; nf++) {
                int cNo = warp_n * 64 + nf * 8 + grp;
                b[nf][0] = Bs[k0 + thr][cNo];
                b[nf][1] = Bs[k0 + 4 + thr][cNo];
            }
#pragma unroll
            for (int mf = 0; mf < 2; mf++)
#pragma unroll
                for (int nf = 0; nf < 8; nf++)
                    mma_tf32(acc[mf][nf], a[mf], b[nf]);
        }
        __syncthreads();
    }

#pragma unroll
    for (int mf = 0; mf < 2; mf++) {
        int r0 = mbase + warp_m * 32 + mf * 16 + grp;
        int r1 = r0 + 8;
        float s0 = (r0 < N_NODES) ? g_dinv[r0] : 0.f;
        float s1 = (r1 < N_NODES) ? g_dinv[r1] : 0.f;
#pragma unroll
        for (int nf = 0; nf < 8; nf++) {
            int cNo = warp_n * 64 + nf * 8 + thr * 2;
            if (r0 < N_NODES)
                *(half2*)(g_h1 + r0 * F1 + cNo) =
                    __floats2half2_rn(acc[mf][nf][0] * s0, acc[mf][nf][1] * s0);
            if (r1 < N_NODES)
                *(half2*)(g_h1 + r1 * F1 + cNo) =
                    __floats2half2_rn(acc[mf][nf][2] * s1, acc[mf][nf][3] * s1);
        }
    }
}

// ---------------- Gather layer 1 (fused agg + relu + bias): warp per node
// Each lane covers 4 features: reads 4 halves (8 B) per neighbor, fp32 accum.

__global__ void __launch_bounds__(256) k_gather1(const float* __restrict__ b1) {
    int w = (blockIdx.x * blockDim.x + threadIdx.x) >> 5;
    if (w >= N_NODES) return;
    int lane = threadIdx.x & 31;
    int c = w;
    int fo = lane * 4;

    half2 h0 = *(const half2*)(g_h1 + c * F1 + fo);
    half2 h1 = *(const half2*)(g_h1 + c * F1 + fo + 2);
    float2 a0 = __half22float2(h0);
    float2 a1 = __half22float2(h1);
    float4 acc = make_float4(a0.x, a0.y, a1.x, a1.y);   // self-loop term

    int start = g_rowptr[c];
    int end = start + g_deg[c];

    int j = start;
    for (; j + 1 < end; j += 2) {
        int s0 = g_csr[j];
        int s1 = g_csr[j + 1];
        uint2 u0 = *(const uint2*)(g_h1 + s0 * F1 + fo);
        uint2 u1 = *(const uint2*)(g_h1 + s1 * F1 + fo);
        float2 p0 = __half22float2(*(half2*)&u0.x);
        float2 p1 = __half22float2(*(half2*)&u0.y);
        float2 q0 = __half22float2(*(half2*)&u1.x);
        float2 q1 = __half22float2(*(half2*)&u1.y);
        acc.x += p0.x + q0.x;
        acc.y += p0.y + q0.y;
        acc.z += p1.x + q1.x;
        acc.w += p1.y + q1.y;
    }
    if (j < end) {
        int s0 = g_csr[j];
        uint2 u0 = *(const uint2*)(g_h1 + s0 * F1 + fo);
        float2 p0 = __half22float2(*(half2*)&u0.x);
        float2 p1 = __half22float2(*(half2*)&u0.y);
        acc.x += p0.x; acc.y += p0.y; acc.z += p1.x; acc.w += p1.y;
    }

    float s = g_dinv[c];
    float4 bb = *(const float4*)(b1 + fo);
    acc.x = fmaxf(fmaf(s, acc.x, bb.x), 0.f);
    acc.y = fmaxf(fmaf(s, acc.y, bb.y), 0.f);
    acc.z = fmaxf(fmaf(s, acc.z, bb.z), 0.f);
    acc.w = fmaxf(fmaf(s, acc.w, bb.w), 0.f);
    *(half2*)(g_y1 + c * F1 + fo)     = __floats2half2_rn(acc.x, acc.y);
    *(half2*)(g_y1 + c * F1 + fo + 2) = __floats2half2_rn(acc.z, acc.w);
}

// ---------------- GEMM2 (tf32 mma): g_h2 = fp16( (y1 @ W2) * dinv[row] )
// Block tile 128x64, 8 warps in 8(m) x 1(n), warp tile 16x64.

__global__ void __launch_bounds__(256) k_gemm2(const float* __restrict__ W) {
    __shared__ unsigned As[128][36];   // [m][k]
    __shared__ unsigned Bs[32][68];    // [k][n]
    int tid = threadIdx.x;
    int lane = tid & 31;
    int wid = tid >> 5;
    int grp = lane >> 2;
    int thr = lane & 3;
    int mbase = blockIdx.x * 128;

    float acc[8][4];
#pragma unroll
    for (int nf = 0; nf < 8; nf++)
#pragma unroll
        for (int q = 0; q < 4; q++) acc[nf][q] = 0.f;

    for (int kt = 0; kt < F1; kt += 32) {
        // A: read fp16 y1, convert to tf32
#pragma unroll
        for (int i = 0; i < 4; i++) {
            int idx4 = tid + i * 256;
            int m = idx4 >> 3;
            int kk = (idx4 & 7) * 4;
            int gm = mbase + m;
            float2 p0 = make_float2(0.f, 0.f), p1 = make_float2(0.f, 0.f);
            if (gm < N_NODES) {
                uint2 u = *(const uint2*)(g_y1 + gm * F1 + kt + kk);
                p0 = __half22float2(*(half2*)&u.x);
                p1 = __half22float2(*(half2*)&u.y);
            }
            uint4 t;
            t.x = f2tf32(p0.x); t.y = f2tf32(p0.y); t.z = f2tf32(p1.x); t.w = f2tf32(p1.y);
            *(uint4*)(&As[m][kk]) = t;
        }
#pragma unroll
        for (int i = 0; i < 2; i++) {
            int idx4 = tid + i * 256;
            int k = idx4 >> 4;
            int nn = (idx4 & 15) * 4;
            float4 v = *(const float4*)(W + (kt + k) * F2 + nn);
            uint4 u;
            u.x = f2tf32(v.x); u.y = f2tf32(v.y); u.z = f2tf32(v.z); u.w = f2tf32(v.w);
            *(uint4*)(&Bs[k][nn]) = u;
        }
        __syncthreads();

#pragma unroll
        for (int k0 = 0; k0 < 32; k0 += 8) {
            unsigned a[4];
            int r = wid * 16 + grp;
            a[0] = As[r][k0 + thr];
            a[1] = As[r + 8][k0 + thr];
            a[2] = As[r][k0 + 4 + thr];
            a[3] = As[r + 8][k0 + 4 + thr];
            unsigned b[8][2];
#pragma unroll
            for (int nf = 0; nf < 8; nf++) {
                int cNo = nf * 8 + grp;
                b[nf][0] = Bs[k0 + thr][cNo];
                b[nf][1] = Bs[k0 + 4 + thr][cNo];
            }
#pragma unroll
            for (int nf = 0; nf < 8; nf++)
                mma_tf32(acc[nf], a, b[nf]);
        }
        __syncthreads();
    }

    int r0 = mbase + wid * 16 + grp;
    int r1 = r0 + 8;
    float s0 = (r0 < N_NODES) ? g_dinv[r0] : 0.f;
    float s1 = (r1 < N_NODES) ? g_dinv[r1] : 0.f;
#pragma unroll
    for (int nf = 0; nf < 8; nf++) {
        int cNo = nf * 8 + thr * 2;
        if (r0 < N_NODES)
            *(half2*)(g_h2 + r0 * F2 + cNo) =
                __floats2half2_rn(acc[nf][0] * s0, acc[nf][1] * s0);
        if (r1 < N_NODES)
            *(half2*)(g_h2 + r1 * F2 + cNo) =
                __floats2half2_rn(acc[nf][2] * s1, acc[nf][3] * s1);
    }
}

// ---------------- Gather layer 2 (fused agg + bias): warp per node
// Each lane covers 2 features: reads 2 halves (4 B) per neighbor, fp32 accum.

__global__ void __launch_bounds__(256) k_gather2(float* __restrict__ out,
                                                 const float* __restrict__ b2) {
    int w = (blockIdx.x * blockDim.x + threadIdx.x) >> 5;
    if (w >= N_NODES) return;
    int lane = threadIdx.x & 31;
    int c = w;
    int fo = lane * 2;

    float2 acc = __half22float2(*(const half2*)(g_h2 + c * F2 + fo));
    int start = g_rowptr[c];
    int end = start + g_deg[c];

    int j = start;
    for (; j + 1 < end; j += 2) {
        int s0 = g_csr[j];
        int s1 = g_csr[j + 1];
        float2 v0 = __half22float2(*(const half2*)(g_h2 + s0 * F2 + fo));
        float2 v1 = __half22float2(*(const half2*)(g_h2 + s1 * F2 + fo));
        acc.x += v0.x + v1.x;
        acc.y += v0.y + v1.y;
    }
    if (j < end) {
        int s0 = g_csr[j];
        float2 v0 = __half22float2(*(const half2*)(g_h2 + s0 * F2 + fo));
        acc.x += v0.x; acc.y += v0.y;
    }

    float s = g_dinv[c];
    float2 bb = *(const float2*)(b2 + fo);
    out[c * F2 + fo + 0] = fmaf(s, acc.x, bb.x);
    out[c * F2 + fo + 1] = fmaf(s, acc.y, bb.y);
}

extern "C" void kernel_launch(void* const* d_in, const int* in_sizes, int n_in,
                              void* d_out, int out_size) {
    const float* x  = (const float*)d_in[0];
    const void*  ei = d_in[1];
    const float* W1 = (const float*)d_in[2];
    const float* b1 = (const float*)d_in[3];
    const float* W2 = (const float*)d_in[4];
    const float* b2 = (const float*)d_in[5];
    float* out = (float*)d_out;

    int E = in_sizes[1] / 2;
    if (E > MAX_E) E = MAX_E;

    k_zero_deg<<<(N_NODES + 255) / 256, 256>>>();
    k_detect<<<1, 256>>>((const long long*)ei);
    k_prep_edges<<<(E + 255) / 256, 256>>>(ei, E);
    k_dinv<<<(N_NODES + 255) / 256, 256>>>();

    k_scan_block<<<NB, 256>>>();
    k_scan_top<<<1, 512>>>();
    k_scan_add<<<(N_NODES + 255) / 256, 256>>>();
    k_fill<<<(E + 255) / 256, 256>>>(E);

    k_gemm1<<<(N_NODES + 127) / 128, 256>>>(x, W1);
    k_gather1<<<(N_NODES * 32 + 255) / 256, 256>>>(b1);
    k_gemm2<<<(N_NODES + 127) / 128, 256>>>(W2);
    k_gather2<<<(N_NODES * 32 + 255) / 256, 256>>>(out, b2);
}

// round 11
// speedup vs baseline: 5.0164x; 1.1414x over previous
#include <cuda_runtime.h>
#include <cuda_fp16.h>

#define N_NODES 100000
#define F0 256
#define F1 128
#define F2 64
#define MAX_E 1600000
#define NB 391   // ceil(N_NODES/256)

// Scratch (allocation-free rule: __device__ globals). 16B-aligned for vector access.
__device__ int   g_is_i32 = 0;       // sticky: same input -> same value every call
__device__ int   g_deg[N_NODES];
__device__ float g_dinv[N_NODES];
__device__ int   g_row32[MAX_E];
__device__ int   g_col32[MAX_E];
__device__ int   g_csr[MAX_E];
__device__ int   g_pref[N_NODES];
__device__ int   g_bsum[NB];
__device__ int   g_boff[NB];
__device__ int   g_rowptr[N_NODES];
__device__ int   g_fill[N_NODES];
__device__ __align__(16) __half g_h1[N_NODES * F1];
__device__ __align__(16) __half g_y1[N_NODES * F1];
__device__ __align__(16) __half g_h2[N_NODES * F2];

// ---------------- tf32 helpers ----------------

__device__ __forceinline__ unsigned f2tf32(float f) {
    unsigned u;
    asm("cvt.rna.tf32.f32 %0, %1;" : "=r"(u) : "f"(f));
    return u;
}

__device__ __forceinline__ void mma_tf32(float* c, const unsigned* a, const unsigned* b) {
    asm volatile(
        "mma.sync.aligned.m16n8k8.row.col.f32.tf32.tf32.f32 "
        "{%0,%1,%2,%3}, {%4,%5,%6,%7}, {%8,%9}, {%0,%1,%2,%3};\n"
        : "+f"(c[0]), "+f"(c[1]), "+f"(c[2]), "+f"(c[3])
        : "r"(a[0]), "r"(a[1]), "r"(a[2]), "r"(a[3]), "r"(b[0]), "r"(b[1]));
}

// ---------------- fused init: zero degrees + dtype detect ----------------

__global__ void k_init(const long long* __restrict__ ei) {
    int i = blockIdx.x * blockDim.x + threadIdx.x;
    if (i < N_NODES) g_deg[i] = 0;
    if (blockIdx.x == 0) {
        long long v = ei[threadIdx.x];
        if (v < 0 || v >= N_NODES) g_is_i32 = 1;   // sticky, deterministic
    }
}

__global__ void k_prep_edges(const void* __restrict__ eiv, int E) {
    int e = blockIdx.x * blockDim.x + threadIdx.x;
    if (e >= E) return;
    int r, c;
    if (g_is_i32) {
        const int* p = (const int*)eiv;
        r = p[e]; c = p[E + e];
    } else {
        const long long* p = (const long long*)eiv;
        r = (int)p[e]; c = (int)p[E + e];
    }
    r = min(max(r, 0), N_NODES - 1);
    c = min(max(c, 0), N_NODES - 1);
    g_row32[e] = r;
    g_col32[e] = c;
    atomicAdd(&g_deg[c], 1);
}

// ---------------- CSR build (dinv fused into block scan) ----------------

__global__ void k_scan_block() {
    __shared__ int s[256];
    int tid = threadIdx.x;
    int i = blockIdx.x * 256 + tid;
    int v = (i < N_NODES) ? g_deg[i] : 0;
    if (i < N_NODES) g_dinv[i] = rsqrtf((float)(v + 1));
    s[tid] = v;
    __syncthreads();
#pragma unroll
    for (int d = 1; d < 256; d <<= 1) {
        int t = (tid >= d) ? s[tid - d] : 0;
        __syncthreads();
        s[tid] += t;
        __syncthreads();
    }
    if (i < N_NODES) g_pref[i] = s[tid] - v;
    if (tid == 255) g_bsum[blockIdx.x] = s[255];
}

__global__ void k_scan_top() {
    __shared__ int s[512];
    int tid = threadIdx.x;
    int v = (tid < NB) ? g_bsum[tid] : 0;
    s[tid] = v;
    __syncthreads();
#pragma unroll
    for (int d = 1; d < 512; d <<= 1) {
        int t = (tid >= d) ? s[tid - d] : 0;
        __syncthreads();
        s[tid] += t;
        __syncthreads();
    }
    if (tid < NB) g_boff[tid] = s[tid] - v;
}

__global__ void k_scan_add() {
    int i = blockIdx.x * blockDim.x + threadIdx.x;
    if (i < N_NODES) {
        int rp = g_pref[i] + g_boff[i >> 8];
        g_rowptr[i] = rp;
        g_fill[i] = rp;
    }
}

__global__ void k_fill(int E) {
    int e = blockIdx.x * blockDim.x + threadIdx.x;
    if (e >= E) return;
    int c = g_col32[e];
    int pos = atomicAdd(&g_fill[c], 1);
    g_csr[pos] = g_row32[e];
}

// ---------------- GEMM1 (tf32 mma): g_h1 = fp16( (x @ W1) * dinv[row] )

__global__ void __launch_bounds__(256) k_gemm1(const float* __restrict__ x,
                                               const float* __restrict__ W) {
    __shared__ unsigned As[128][36];
    __shared__ unsigned Bs[32][132];
    int tid = threadIdx.x;
    int lane = tid & 31;
    int wid = tid >> 5;
    int warp_m = wid & 3;
    int warp_n = wid >> 2;
    int grp = lane >> 2;
    int thr = lane & 3;
    int mbase = blockIdx.x * 128;

    float acc[2][8][4];
#pragma unroll
    for (int mf = 0; mf < 2; mf++)
#pragma unroll
        for (int nf = 0; nf < 8; nf++)
#pragma unroll
            for (int q = 0; q < 4; q++) acc[mf][nf][q] = 0.f;

    for (int kt = 0; kt < F0; kt += 32) {
#pragma unroll
        for (int i = 0; i < 4; i++) {
            int idx4 = tid + i * 256;
            int m = idx4 >> 3;
            int kk = (idx4 & 7) * 4;
            int gm = mbase + m;
            float4 v = make_float4(0.f, 0.f, 0.f, 0.f);
            if (gm < N_NODES) v = *(const float4*)(x + gm * F0 + kt + kk);
            uint4 u;
            u.x = f2tf32(v.x); u.y = f2tf32(v.y); u.z = f2tf32(v.z); u.w = f2tf32(v.w);
            *(uint4*)(&As[m][kk]) = u;
        }
#pragma unroll
        for (int i = 0; i < 4; i++) {
            int idx4 = tid + i * 256;
            int k = idx4 >> 5;
            int nn = (idx4 & 31) * 4;
            float4 v = *(const float4*)(W + (kt + k) * F1 + nn);
            uint4 u;
            u.x = f2tf32(v.x); u.y = f2tf32(v.y); u.z = f2tf32(v.z); u.w = f2tf32(v.w);
            *(uint4*)(&Bs[k][nn]) = u;
        }
        __syncthreads();

#pragma unroll
        for (int k0 = 0; k0 < 32; k0 += 8) {
            unsigned a[2][4];
#pragma unroll
            for (int mf = 0; mf < 2; mf++) {
                int r = warp_m * 32 + mf * 16 + grp;
                a[mf][0] = As[r][k0 + thr];
                a[mf][1] = As[r + 8][k0 + thr];
                a[mf][2] = As[r][k0 + 4 + thr];
                a[mf][3] = As[r + 8][k0 + 4 + thr];
            }
            unsigned b[8][2];
#pragma unroll
            for (int nf = 0; nf < 8; nf++) {
                int cNo = warp_n * 64 + nf * 8 + grp;
                b[nf][0] = Bs[k0 + thr][cNo];
                b[nf][1] = Bs[k0 + 4 + thr][cNo];
            }
#pragma unroll
            for (int mf = 0; mf < 2; mf++)
#pragma unroll
                for (int nf = 0; nf < 8; nf++)
                    mma_tf32(acc[mf][nf], a[mf], b[nf]);
        }
        __syncthreads();
    }

#pragma unroll
    for (int mf = 0; mf < 2; mf++) {
        int r0 = mbase + warp_m * 32 + mf * 16 + grp;
        int r1 = r0 + 8;
        float s0 = (r0 < N_NODES) ? g_dinv[r0] : 0.f;
        float s1 = (r1 < N_NODES) ? g_dinv[r1] : 0.f;
#pragma unroll
        for (int nf = 0; nf < 8; nf++) {
            int cNo = warp_n * 64 + nf * 8 + thr * 2;
            if (r0 < N_NODES)
                *(half2*)(g_h1 + r0 * F1 + cNo) =
                    __floats2half2_rn(acc[mf][nf][0] * s0, acc[mf][nf][1] * s0);
            if (r1 < N_NODES)
                *(half2*)(g_h1 + r1 * F1 + cNo) =
                    __floats2half2_rn(acc[mf][nf][2] * s1, acc[mf][nf][3] * s1);
        }
    }
}

// ---------------- Gather layer 1: warp per node, 4-way unroll for MLP

__global__ void __launch_bounds__(256) k_gather1(const float* __restrict__ b1) {
    int w = (blockIdx.x * blockDim.x + threadIdx.x) >> 5;
    if (w >= N_NODES) return;
    int lane = threadIdx.x & 31;
    int c = w;
    int fo = lane * 4;

    float2 a0 = __half22float2(*(const half2*)(g_h1 + c * F1 + fo));
    float2 a1 = __half22float2(*(const half2*)(g_h1 + c * F1 + fo + 2));
    float4 acc = make_float4(a0.x, a0.y, a1.x, a1.y);   // self-loop term

    int start = g_rowptr[c];
    int end = start + g_deg[c];

    int j = start;
    for (; j + 4 <= end; j += 4) {
        int i0 = g_csr[j], i1 = g_csr[j + 1], i2 = g_csr[j + 2], i3 = g_csr[j + 3];
        uint2 u0 = *(const uint2*)(g_h1 + i0 * F1 + fo);
        uint2 u1 = *(const uint2*)(g_h1 + i1 * F1 + fo);
        uint2 u2 = *(const uint2*)(g_h1 + i2 * F1 + fo);
        uint2 u3 = *(const uint2*)(g_h1 + i3 * F1 + fo);
        float2 p;
        p = __half22float2(*(half2*)&u0.x); acc.x += p.x; acc.y += p.y;
        p = __half22float2(*(half2*)&u0.y); acc.z += p.x; acc.w += p.y;
        p = __half22float2(*(half2*)&u1.x); acc.x += p.x; acc.y += p.y;
        p = __half22float2(*(half2*)&u1.y); acc.z += p.x; acc.w += p.y;
        p = __half22float2(*(half2*)&u2.x); acc.x += p.x; acc.y += p.y;
        p = __half22float2(*(half2*)&u2.y); acc.z += p.x; acc.w += p.y;
        p = __half22float2(*(half2*)&u3.x); acc.x += p.x; acc.y += p.y;
        p = __half22float2(*(half2*)&u3.y); acc.z += p.x; acc.w += p.y;
    }
    for (; j < end; j++) {
        int i0 = g_csr[j];
        uint2 u0 = *(const uint2*)(g_h1 + i0 * F1 + fo);
        float2 p;
        p = __half22float2(*(half2*)&u0.x); acc.x += p.x; acc.y += p.y;
        p = __half22float2(*(half2*)&u0.y); acc.z += p.x; acc.w += p.y;
    }

    float s = g_dinv[c];
    float4 bb = *(const float4*)(b1 + fo);
    acc.x = fmaxf(fmaf(s, acc.x, bb.x), 0.f);
    acc.y = fmaxf(fmaf(s, acc.y, bb.y), 0.f);
    acc.z = fmaxf(fmaf(s, acc.z, bb.z), 0.f);
    acc.w = fmaxf(fmaf(s, acc.w, bb.w), 0.f);
    *(half2*)(g_y1 + c * F1 + fo)     = __floats2half2_rn(acc.x, acc.y);
    *(half2*)(g_y1 + c * F1 + fo + 2) = __floats2half2_rn(acc.z, acc.w);
}

// ---------------- GEMM2 (tf32 mma): g_h2 = fp16( (y1 @ W2) * dinv[row] )

__global__ void __launch_bounds__(256) k_gemm2(const float* __restrict__ W) {
    __shared__ unsigned As[128][36];
    __shared__ unsigned Bs[32][68];
    int tid = threadIdx.x;
    int lane = tid & 31;
    int wid = tid >> 5;
    int grp = lane >> 2;
    int thr = lane & 3;
    int mbase = blockIdx.x * 128;

    float acc[8][4];
#pragma unroll
    for (int nf = 0; nf < 8; nf++)
#pragma unroll
        for (int q = 0; q < 4; q++) acc[nf][q] = 0.f;

    for (int kt = 0; kt < F1; kt += 32) {
#pragma unroll
        for (int i = 0; i < 4; i++) {
            int idx4 = tid + i * 256;
            int m = idx4 >> 3;
            int kk = (idx4 & 7) * 4;
            int gm = mbase + m;
            float2 p0 = make_float2(0.f, 0.f), p1 = make_float2(0.f, 0.f);
            if (gm < N_NODES) {
                uint2 u = *(const uint2*)(g_y1 + gm * F1 + kt + kk);
                p0 = __half22float2(*(half2*)&u.x);
                p1 = __half22float2(*(half2*)&u.y);
            }
            uint4 t;
            t.x = f2tf32(p0.x); t.y = f2tf32(p0.y); t.z = f2tf32(p1.x); t.w = f2tf32(p1.y);
            *(uint4*)(&As[m][kk]) = t;
        }
#pragma unroll
        for (int i = 0; i < 2; i++) {
            int idx4 = tid + i * 256;
            int k = idx4 >> 4;
            int nn = (idx4 & 15) * 4;
            float4 v = *(const float4*)(W + (kt + k) * F2 + nn);
            uint4 u;
            u.x = f2tf32(v.x); u.y = f2tf32(v.y); u.z = f2tf32(v.z); u.w = f2tf32(v.w);
            *(uint4*)(&Bs[k][nn]) = u;
        }
        __syncthreads();

#pragma unroll
        for (int k0 = 0; k0 < 32; k0 += 8) {
            unsigned a[4];
            int r = wid * 16 + grp;
            a[0] = As[r][k0 + thr];
            a[1] = As[r + 8][k0 + thr];
            a[2] = As[r][k0 + 4 + thr];
            a[3] = As[r + 8][k0 + 4 + thr];
            unsigned b[8][2];
#pragma unroll
            for (int nf = 0; nf < 8; nf++) {
                int cNo = nf * 8 + grp;
                b[nf][0] = Bs[k0 + thr][cNo];
                b[nf][1] = Bs[k0 + 4 + thr][cNo];
            }
#pragma unroll
            for (int nf = 0; nf < 8; nf++)
                mma_tf32(acc[nf], a, b[nf]);
        }
        __syncthreads();
    }

    int r0 = mbase + wid * 16 + grp;
    int r1 = r0 + 8;
    float s0 = (r0 < N_NODES) ? g_dinv[r0] : 0.f;
    float s1 = (r1 < N_NODES) ? g_dinv[r1] : 0.f;
#pragma unroll
    for (int nf = 0; nf < 8; nf++) {
        int cNo = nf * 8 + thr * 2;
        if (r0 < N_NODES)
            *(half2*)(g_h2 + r0 * F2 + cNo) =
                __floats2half2_rn(acc[nf][0] * s0, acc[nf][1] * s0);
        if (r1 < N_NODES)
            *(half2*)(g_h2 + r1 * F2 + cNo) =
                __floats2half2_rn(acc[nf][2] * s1, acc[nf][3] * s1);
    }
}

// ---------------- Gather layer 2: warp per node, 4-way unroll

__global__ void __launch_bounds__(256) k_gather2(float* __restrict__ out,
                                                 const float* __restrict__ b2) {
    int w = (blockIdx.x * blockDim.x + threadIdx.x) >> 5;
    if (w >= N_NODES) return;
    int lane = threadIdx.x & 31;
    int c = w;
    int fo = lane * 2;

    float2 acc = __half22float2(*(const half2*)(g_h2 + c * F2 + fo));
    int start = g_rowptr[c];
    int end = start + g_deg[c];

    int j = start;
    for (; j + 4 <= end; j += 4) {
        int i0 = g_csr[j], i1 = g_csr[j + 1], i2 = g_csr[j + 2], i3 = g_csr[j + 3];
        float2 v0 = __half22float2(*(const half2*)(g_h2 + i0 * F2 + fo));
        float2 v1 = __half22float2(*(const half2*)(g_h2 + i1 * F2 + fo));
        float2 v2 = __half22float2(*(const half2*)(g_h2 + i2 * F2 + fo));
        float2 v3 = __half22float2(*(const half2*)(g_h2 + i3 * F2 + fo));
        acc.x += (v0.x + v1.x) + (v2.x + v3.x);
        acc.y += (v0.y + v1.y) + (v2.y + v3.y);
    }
    for (; j < end; j++) {
        float2 v0 = __half22float2(*(const half2*)(g_h2 + g_csr[j] * F2 + fo));
        acc.x += v0.x; acc.y += v0.y;
    }

    float s = g_dinv[c];
    float2 bb = *(const float2*)(b2 + fo);
    out[c * F2 + fo + 0] = fmaf(s, acc.x, bb.x);
    out[c * F2 + fo + 1] = fmaf(s, acc.y, bb.y);
}

extern "C" void kernel_launch(void* const* d_in, const int* in_sizes, int n_in,
                              void* d_out, int out_size) {
    const float* x  = (const float*)d_in[0];
    const void*  ei = d_in[1];
    const float* W1 = (const float*)d_in[2];
    const float* b1 = (const float*)d_in[3];
    const float* W2 = (const float*)d_in[4];
    const float* b2 = (const float*)d_in[5];
    float* out = (float*)d_out;

    int E = in_sizes[1] / 2;
    if (E > MAX_E) E = MAX_E;

    // One-time side stream + fork/join events (created on first call, outside
    // graph capture; no device-memory allocation involved).
    static cudaStream_t s_b = 0;
    static cudaEvent_t  e_fork = 0, e_join = 0;
    static int s_ok = -1;
    if (s_ok < 0) {
        s_ok = (cudaStreamCreateWithFlags(&s_b, cudaStreamNonBlocking) == cudaSuccess &&
                cudaEventCreateWithFlags(&e_fork, cudaEventDisableTiming) == cudaSuccess &&
                cudaEventCreateWithFlags(&e_join, cudaEventDisableTiming) == cudaSuccess)
                   ? 1 : 0;
    }

    k_init<<<(N_NODES + 255) / 256, 256>>>((const long long*)ei);
    k_prep_edges<<<(E + 255) / 256, 256>>>(ei, E);
    k_scan_block<<<NB, 256>>>();   // also writes g_dinv

    if (s_ok) {
        // Fork: CSR finalization runs concurrently with GEMM1.
        cudaEventRecord(e_fork, 0);
        cudaStreamWaitEvent(s_b, e_fork, 0);
        k_scan_top<<<1, 512, 0, s_b>>>();
        k_scan_add<<<(N_NODES + 255) / 256, 256, 0, s_b>>>();
        k_fill<<<(E + 255) / 256, 256, 0, s_b>>>(E);
        cudaEventRecord(e_join, s_b);

        k_gemm1<<<(N_NODES + 127) / 128, 256>>>(x, W1);

        cudaStreamWaitEvent(0, e_join, 0);   // join before gather needs CSR
    } else {
        k_scan_top<<<1, 512>>>();
        k_scan_add<<<(N_NODES + 255) / 256, 256>>>();
        k_fill<<<(E + 255) / 256, 256>>>(E);
        k_gemm1<<<(N_NODES + 127) / 128, 256>>>(x, W1);
    }

    k_gather1<<<(N_NODES * 32 + 255) / 256, 256>>>(b1);
    k_gemm2<<<(N_NODES + 127) / 128, 256>>>(W2);
    k_gather2<<<(N_NODES * 32 + 255) / 256, 256>>>(out, b2);
}